// round 7
// baseline (speedup 1.0000x reference)
#include <cuda_runtime.h>

// AELoss: pred/target (64,4,256,256) fp32, match (64,128,2,2) int32.
// out[0] = 0.25 * sum_b pull_b, out[1] = 0.25 * sum_b push_b
//
// pull_b = sum_{n,c} (tl-br)^2 / 2 / N        (since tl-me = (tl-br)/2)
// push_b = sum_{i!=j} relu(1 - |s_i - s_j|) / (N*(N-1)),  s_i = sum_c (tl+br)/2
//
// Single graph node. out[] zeroing is folded into the kernel:
//   start: every CTA zeroes out[], fences, increments g_zc   (overlapped)
//   end:   before RED.ADDing, confirm g_zc==64 (one L2 read; always true by then)
// Race-free: an add can only happen after ALL zero-stores are fenced+counted.
// g_zc/g_done reset by the last-finishing CTA -> every graph replay identical.

#define B_IMGS 64
#define N_KP   128
#define C_CH   4
#define HW     65536   // 256*256
#define W_DIM  256

__device__ unsigned int g_zc;     // CTAs that have zeroed out[]
__device__ unsigned int g_done;   // CTAs that have finished adding

__device__ __forceinline__ unsigned int ld_cg_u32(const unsigned int* p) {
    unsigned int v;
    asm volatile("ld.global.cg.u32 %0, [%1];" : "=r"(v) : "l"(p) : "memory");
    return v;
}

__global__ __launch_bounds__(N_KP, 1)
void ae_kernel(const float* __restrict__ pred,
               const float* __restrict__ target,
               const int*   __restrict__ match,
               float*       __restrict__ out) {
    const int b = blockIdx.x;
    const int n = threadIdx.x;

    __shared__ float s_me[N_KP];
    __shared__ float s_red[8];   // 4 warps x 2 values

    // ---- phase 0: cooperative zeroing of out[] (overlaps the gather) ----
    if (n == 0) {
        __stcg(&out[0], 0.0f);
        __stcg(&out[1], 0.0f);
        __threadfence();           // zero-stores visible before the counter inc
        atomicAdd(&g_zc, 1u);      // fire-and-forget
    }

    // match[b, n, {tl,br}, {y,x}] -- one int4 per (b,n)
    const int4 m = __ldg(reinterpret_cast<const int4*>(match) + b * N_KP + n);
    const int tl_off = m.x * W_DIM + m.y;
    const int br_off = m.z * W_DIM + m.w;

    const float* __restrict__ p = pred   + (size_t)b * C_CH * HW;
    const float* __restrict__ t = target + (size_t)b * C_CH * HW;

    float pull = 0.0f;
    float s    = 0.0f;
    #pragma unroll
    for (int c = 0; c < C_CH; ++c) {
        const float tl = __ldg(p + c * HW + tl_off);
        const float br = __ldg(t + c * HW + br_off);
        const float d = tl - br;
        pull += 0.5f * d * d;
        s    += 0.5f * (tl + br);
    }
    s_me[n] = s;
    __syncthreads();

    // push over all j (smem broadcast, vectorized); subtract the j==n term (==1)
    float push = -1.0f;
    const float4* __restrict__ s4 = reinterpret_cast<const float4*>(s_me);
    #pragma unroll
    for (int j = 0; j < N_KP / 4; ++j) {
        const float4 v = s4[j];
        push += fmaxf(0.0f, 1.0f - fabsf(s - v.x));
        push += fmaxf(0.0f, 1.0f - fabsf(s - v.y));
        push += fmaxf(0.0f, 1.0f - fabsf(s - v.z));
        push += fmaxf(0.0f, 1.0f - fabsf(s - v.w));
    }

    // block reduction of (pull, push)
    #pragma unroll
    for (int off = 16; off > 0; off >>= 1) {
        pull += __shfl_down_sync(0xFFFFFFFFu, pull, off);
        push += __shfl_down_sync(0xFFFFFFFFu, push, off);
    }
    const int warp = n >> 5;
    const int lane = n & 31;
    if (lane == 0) {
        s_red[warp]     = pull;
        s_red[4 + warp] = push;
    }
    __syncthreads();

    // ---- phase 2: confirm all zeroes landed, then fire-and-forget adds ----
    if (n == 0) {
        const float pu = s_red[0] + s_red[1] + s_red[2] + s_red[3];
        const float ph = s_red[4] + s_red[5] + s_red[6] + s_red[7];

        while (ld_cg_u32(&g_zc) < (unsigned)B_IMGS) { }  // always true by now
        __threadfence();   // acquire: order the adds after all zero-stores

        atomicAdd(&out[0], pu * (0.25f / (float)N_KP));
        atomicAdd(&out[1], ph * (0.25f / (float)(N_KP * (N_KP - 1))));

        // last finisher resets the counters for the next graph replay
        const unsigned int o = atomicAdd(&g_done, 1u);
        if (o == (unsigned)(B_IMGS - 1)) {
            g_zc   = 0u;
            g_done = 0u;
        }
    }
}

extern "C" void kernel_launch(void* const* d_in, const int* in_sizes, int n_in,
                              void* d_out, int out_size) {
    const float* pred   = (const float*)d_in[0];
    const float* target = (const float*)d_in[1];
    const int*   match  = (const int*)d_in[2];
    float* out = (float*)d_out;

    ae_kernel<<<B_IMGS, N_KP>>>(pred, target, match, out);
}

// round 8
// speedup vs baseline: 1.0938x; 1.0938x over previous
#include <cuda_runtime.h>

// AELoss: pred/target (64,4,256,256) fp32, match (64,128,2,2) int32.
// out[0] = 0.25 * sum_b pull_b, out[1] = 0.25 * sum_b push_b
//
// pull_b = sum_{n,c} (tl-br)^2 / 2 / N        (since tl-me = (tl-br)/2)
// push_b = sum_{i!=j} relu(1 - |s_i - s_j|) / (N*(N-1)),  s_i = sum_c (tl+br)/2
//
// Structure (measured best, R5): memset graph node zeroes out[] (node cost ~0),
// kernel CTAs fire-and-forget RED.ADD their scaled partials into out[].
// Tail trimmed: per-warp shuffle reduce -> lane-0 RED.ADD directly (no smem
// stage, one __syncthreads total).

#define B_IMGS 64
#define N_KP   128
#define C_CH   4
#define HW     65536   // 256*256
#define W_DIM  256

__global__ __launch_bounds__(N_KP, 1)
void ae_kernel(const float* __restrict__ pred,
               const float* __restrict__ target,
               const int*   __restrict__ match,
               float*       __restrict__ out) {
    const int b = blockIdx.x;
    const int n = threadIdx.x;

    __shared__ float s_me[N_KP];

    // match[b, n, {tl,br}, {y,x}] -- issue this DRAM load first
    const int4 m = __ldg(reinterpret_cast<const int4*>(match) + b * N_KP + n);
    const int tl_off = m.x * W_DIM + m.y;
    const int br_off = m.z * W_DIM + m.w;

    const float* __restrict__ p = pred   + (size_t)b * C_CH * HW;
    const float* __restrict__ t = target + (size_t)b * C_CH * HW;

    float pull = 0.0f;
    float s    = 0.0f;
    #pragma unroll
    for (int c = 0; c < C_CH; ++c) {
        const float tl = __ldg(p + c * HW + tl_off);
        const float br = __ldg(t + c * HW + br_off);
        const float d = tl - br;
        pull += 0.5f * d * d;
        s    += 0.5f * (tl + br);
    }
    s_me[n] = s;
    __syncthreads();

    // push over all j (smem broadcast, vectorized); subtract the j==n term (==1)
    float push = -1.0f;
    const float4* __restrict__ s4 = reinterpret_cast<const float4*>(s_me);
    #pragma unroll
    for (int j = 0; j < N_KP / 4; ++j) {
        const float4 v = s4[j];
        push += fmaxf(0.0f, 1.0f - fabsf(s - v.x));
        push += fmaxf(0.0f, 1.0f - fabsf(s - v.y));
        push += fmaxf(0.0f, 1.0f - fabsf(s - v.z));
        push += fmaxf(0.0f, 1.0f - fabsf(s - v.w));
    }

    // per-warp shuffle reduce, then lane 0 fires RED.ADDs (no smem stage)
    #pragma unroll
    for (int off = 16; off > 0; off >>= 1) {
        pull += __shfl_down_sync(0xFFFFFFFFu, pull, off);
        push += __shfl_down_sync(0xFFFFFFFFu, push, off);
    }
    if ((n & 31) == 0) {
        atomicAdd(&out[0], pull * (0.25f / (float)N_KP));
        atomicAdd(&out[1], push * (0.25f / (float)(N_KP * (N_KP - 1))));
    }
}

extern "C" void kernel_launch(void* const* d_in, const int* in_sizes, int n_in,
                              void* d_out, int out_size) {
    const float* pred   = (const float*)d_in[0];
    const float* target = (const float*)d_in[1];
    const int*   match  = (const int*)d_in[2];
    float* out = (float*)d_out;

    cudaMemsetAsync(out, 0, 2 * sizeof(float));
    ae_kernel<<<B_IMGS, N_KP>>>(pred, target, match, out);
}

// round 10
// speedup vs baseline: 1.0980x; 1.0039x over previous
#include <cuda_runtime.h>

// AELoss: pred/target (64,4,256,256) fp32, match (64,128,2,2) int32.
// out[0] = 0.25 * sum_b pull_b, out[1] = 0.25 * sum_b push_b
//
// pull_b = sum_{n,c} (tl-br)^2 / 2 / N        (since tl-me = (tl-br)/2)
// push_b = sum_{i!=j} relu(1 - |s_i - s_j|) / (N*(N-1)),  s_i = sum_c (tl+br)/2
//
// R8 structure (memset node + fire-and-forget RED.ADD) + L2 evict_last cache
// policy on the gather loads (createpolicy + ld.L2::cache_hint — the form
// ptxas accepts for scalar loads on sm_103a): the ~8.3MB randomly-touched
// working set persists in the 126MB L2 across graph replays.

#define B_IMGS 64
#define N_KP   128
#define C_CH   4
#define HW     65536   // 256*256
#define W_DIM  256

__device__ __forceinline__ unsigned long long mk_evict_last_policy() {
    unsigned long long pol;
    asm volatile("createpolicy.fractional.L2::evict_last.b64 %0, 1.0;" : "=l"(pol));
    return pol;
}

__device__ __forceinline__ float ldg_el(const float* p, unsigned long long pol) {
    float v;
    asm volatile("ld.global.nc.L2::cache_hint.f32 %0, [%1], %2;"
                 : "=f"(v) : "l"(p), "l"(pol));
    return v;
}

__device__ __forceinline__ int4 ldg_el_i4(const int4* p, unsigned long long pol) {
    int4 v;
    asm volatile("ld.global.nc.L2::cache_hint.v4.s32 {%0,%1,%2,%3}, [%4], %5;"
                 : "=r"(v.x), "=r"(v.y), "=r"(v.z), "=r"(v.w) : "l"(p), "l"(pol));
    return v;
}

__global__ __launch_bounds__(N_KP, 1)
void ae_kernel(const float* __restrict__ pred,
               const float* __restrict__ target,
               const int*   __restrict__ match,
               float*       __restrict__ out) {
    const int b = blockIdx.x;
    const int n = threadIdx.x;

    __shared__ float s_me[N_KP];

    const unsigned long long pol = mk_evict_last_policy();

    // match[b, n, {tl,br}, {y,x}] -- first DRAM trip, keep resident in L2
    const int4 m = ldg_el_i4(reinterpret_cast<const int4*>(match) + b * N_KP + n, pol);
    const int tl_off = m.x * W_DIM + m.y;
    const int br_off = m.z * W_DIM + m.w;

    const float* __restrict__ p = pred   + (size_t)b * C_CH * HW;
    const float* __restrict__ t = target + (size_t)b * C_CH * HW;

    float pull = 0.0f;
    float s    = 0.0f;
    #pragma unroll
    for (int c = 0; c < C_CH; ++c) {
        const float tl = ldg_el(p + c * HW + tl_off, pol);
        const float br = ldg_el(t + c * HW + br_off, pol);
        const float d = tl - br;
        pull += 0.5f * d * d;
        s    += 0.5f * (tl + br);
    }
    s_me[n] = s;
    __syncthreads();

    // push over all j (smem broadcast, vectorized); subtract the j==n term (==1)
    float push = -1.0f;
    const float4* __restrict__ s4 = reinterpret_cast<const float4*>(s_me);
    #pragma unroll
    for (int j = 0; j < N_KP / 4; ++j) {
        const float4 v = s4[j];
        push += fmaxf(0.0f, 1.0f - fabsf(s - v.x));
        push += fmaxf(0.0f, 1.0f - fabsf(s - v.y));
        push += fmaxf(0.0f, 1.0f - fabsf(s - v.z));
        push += fmaxf(0.0f, 1.0f - fabsf(s - v.w));
    }

    // per-warp shuffle reduce, then lane 0 fires RED.ADDs (no smem stage)
    #pragma unroll
    for (int off = 16; off > 0; off >>= 1) {
        pull += __shfl_down_sync(0xFFFFFFFFu, pull, off);
        push += __shfl_down_sync(0xFFFFFFFFu, push, off);
    }
    if ((n & 31) == 0) {
        atomicAdd(&out[0], pull * (0.25f / (float)N_KP));
        atomicAdd(&out[1], push * (0.25f / (float)(N_KP * (N_KP - 1))));
    }
}

extern "C" void kernel_launch(void* const* d_in, const int* in_sizes, int n_in,
                              void* d_out, int out_size) {
    const float* pred   = (const float*)d_in[0];
    const float* target = (const float*)d_in[1];
    const int*   match  = (const int*)d_in[2];
    float* out = (float*)d_out;

    cudaMemsetAsync(out, 0, 2 * sizeof(float));
    ae_kernel<<<B_IMGS, N_KP>>>(pred, target, match, out);
}

// round 11
// speedup vs baseline: 1.1024x; 1.0039x over previous
#include <cuda_runtime.h>

// AELoss: pred/target (64,4,256,256) fp32, match (64,128,2,2) int32.
// out[0] = 0.25 * sum_b pull_b, out[1] = 0.25 * sum_b push_b
//
// pull_b = sum_{n,c} (tl-br)^2 / 2 / N        (since tl-me = (tl-br)/2)
// push_b = sum_{i!=j} relu(1 - |s_i - s_j|) / (N*(N-1)),  s_i = sum_c (tl+br)/2
//
// Final structure (measured best over 11 rounds):
//  - memset graph node zeroes out[] (node cost ~0.1us, no in-kernel fences)
//  - one CTA per image, one thread per keypoint, 8 fully-parallel gathers
//  - push term on channel-summed scalars via smem broadcast (O(N^2) scalar)
//  - per-warp shuffle reduce -> lane-0 fire-and-forget RED.ADD into out[]
//    (no read-back tail; this was the single -2us win of the session)
// Kernel is launch-ramp/latency-floor bound: 6.69us kernel + ~1.2us dispatch.

#define B_IMGS 64
#define N_KP   128
#define C_CH   4
#define HW     65536   // 256*256
#define W_DIM  256

__global__ __launch_bounds__(N_KP, 1)
void ae_kernel(const float* __restrict__ pred,
               const float* __restrict__ target,
               const int*   __restrict__ match,
               float*       __restrict__ out) {
    const int b = blockIdx.x;
    const int n = threadIdx.x;

    __shared__ float s_me[N_KP];

    // match[b, n, {tl,br}, {y,x}] -- first memory trip, issued immediately
    const int4 m = __ldg(reinterpret_cast<const int4*>(match) + b * N_KP + n);
    const int tl_off = m.x * W_DIM + m.y;
    const int br_off = m.z * W_DIM + m.w;

    const float* __restrict__ p = pred   + (size_t)b * C_CH * HW;
    const float* __restrict__ t = target + (size_t)b * C_CH * HW;

    float pull = 0.0f;
    float s    = 0.0f;
    #pragma unroll
    for (int c = 0; c < C_CH; ++c) {
        const float tl = __ldg(p + c * HW + tl_off);
        const float br = __ldg(t + c * HW + br_off);
        const float d = tl - br;
        pull += 0.5f * d * d;
        s    += 0.5f * (tl + br);
    }
    s_me[n] = s;
    __syncthreads();

    // push over all j (smem broadcast, vectorized); subtract the j==n term (==1)
    float push = -1.0f;
    const float4* __restrict__ s4 = reinterpret_cast<const float4*>(s_me);
    #pragma unroll
    for (int j = 0; j < N_KP / 4; ++j) {
        const float4 v = s4[j];
        push += fmaxf(0.0f, 1.0f - fabsf(s - v.x));
        push += fmaxf(0.0f, 1.0f - fabsf(s - v.y));
        push += fmaxf(0.0f, 1.0f - fabsf(s - v.z));
        push += fmaxf(0.0f, 1.0f - fabsf(s - v.w));
    }

    // per-warp shuffle reduce, then lane 0 fires RED.ADDs (no read-back tail)
    #pragma unroll
    for (int off = 16; off > 0; off >>= 1) {
        pull += __shfl_down_sync(0xFFFFFFFFu, pull, off);
        push += __shfl_down_sync(0xFFFFFFFFu, push, off);
    }
    if ((n & 31) == 0) {
        atomicAdd(&out[0], pull * (0.25f / (float)N_KP));
        atomicAdd(&out[1], push * (0.25f / (float)(N_KP * (N_KP - 1))));
    }
}

extern "C" void kernel_launch(void* const* d_in, const int* in_sizes, int n_in,
                              void* d_out, int out_size) {
    const float* pred   = (const float*)d_in[0];
    const float* target = (const float*)d_in[1];
    const int*   match  = (const int*)d_in[2];
    float* out = (float*)d_out;

    cudaMemsetAsync(out, 0, 2 * sizeof(float));
    ae_kernel<<<B_IMGS, N_KP>>>(pred, target, match, out);
}

// round 12
// speedup vs baseline: 1.1067x; 1.0040x over previous
#include <cuda_runtime.h>

// AELoss: pred/target (64,4,256,256) fp32, match (64,128,2,2) int32.
// out[0] = 0.25 * sum_b pull_b, out[1] = 0.25 * sum_b push_b
//
// pull_b = sum_{n,c} (tl-br)^2 / 2 / N        (since tl-me = (tl-br)/2)
// push_b = sum_{i!=j} relu(1 - |s_i - s_j|) / (N*(N-1)),  s_i = sum_c (tl+br)/2
//
// FINAL (best measured: 7.968us total, kernel 6.688us).
// Structure and why each piece survived 12 rounds of adjudication:
//  - memset graph node zeroes out[] (~0.1-0.3us, beats every in-kernel
//    zeroing protocol tried; R7's fenced version cost +1.1us)
//  - one CTA per image, one thread per keypoint, 8 fully-parallel gathers
//    (cluster-split gathers: neutral; L2 evict_last policy: neutral)
//  - push on channel-summed scalars via vectorized smem broadcast
//    (ILP splits and j-range halving: in-kernel neutral — body is slack)
//  - warp shuffle reduce -> smem -> single-thread fire-and-forget RED.ADDs
//    (read-back reduction tails cost +1.3-2us; RED tail was the session win)
// Remaining cost is launch ramp + graph dispatch: not .cu-addressable.

#define B_IMGS 64
#define N_KP   128
#define C_CH   4
#define HW     65536   // 256*256
#define W_DIM  256

__global__ __launch_bounds__(N_KP, 1)
void ae_kernel(const float* __restrict__ pred,
               const float* __restrict__ target,
               const int*   __restrict__ match,
               float*       __restrict__ out) {
    const int b = blockIdx.x;
    const int n = threadIdx.x;

    __shared__ float s_me[N_KP];
    __shared__ float s_red[8];   // 4 warps x 2 values

    // match[b, n, {tl,br}, {y,x}] -- one int4 per (b,n), issued first
    const int4 m = __ldg(reinterpret_cast<const int4*>(match) + b * N_KP + n);
    const int tl_off = m.x * W_DIM + m.y;
    const int br_off = m.z * W_DIM + m.w;

    const float* __restrict__ p = pred   + (size_t)b * C_CH * HW;
    const float* __restrict__ t = target + (size_t)b * C_CH * HW;

    float pull = 0.0f;
    float s    = 0.0f;
    #pragma unroll
    for (int c = 0; c < C_CH; ++c) {
        const float tl = __ldg(p + c * HW + tl_off);
        const float br = __ldg(t + c * HW + br_off);
        const float d = tl - br;
        pull += 0.5f * d * d;
        s    += 0.5f * (tl + br);
    }
    s_me[n] = s;
    __syncthreads();

    // push over all j (smem broadcast, vectorized); subtract the j==n term (==1)
    float push = -1.0f;
    const float4* __restrict__ s4 = reinterpret_cast<const float4*>(s_me);
    #pragma unroll
    for (int j = 0; j < N_KP / 4; ++j) {
        const float4 v = s4[j];
        push += fmaxf(0.0f, 1.0f - fabsf(s - v.x));
        push += fmaxf(0.0f, 1.0f - fabsf(s - v.y));
        push += fmaxf(0.0f, 1.0f - fabsf(s - v.z));
        push += fmaxf(0.0f, 1.0f - fabsf(s - v.w));
    }

    // block reduction of (pull, push)
    #pragma unroll
    for (int off = 16; off > 0; off >>= 1) {
        pull += __shfl_down_sync(0xFFFFFFFFu, pull, off);
        push += __shfl_down_sync(0xFFFFFFFFu, push, off);
    }
    const int warp = n >> 5;
    const int lane = n & 31;
    if (lane == 0) {
        s_red[warp]     = pull;
        s_red[4 + warp] = push;
    }
    __syncthreads();

    // fire-and-forget global reduction: 2 RED.ADD per CTA, no read-back tail
    if (n == 0) {
        const float pu = s_red[0] + s_red[1] + s_red[2] + s_red[3];
        const float ph = s_red[4] + s_red[5] + s_red[6] + s_red[7];
        atomicAdd(&out[0], pu * (0.25f / (float)N_KP));
        atomicAdd(&out[1], ph * (0.25f / (float)(N_KP * (N_KP - 1))));
    }
}

extern "C" void kernel_launch(void* const* d_in, const int* in_sizes, int n_in,
                              void* d_out, int out_size) {
    const float* pred   = (const float*)d_in[0];
    const float* target = (const float*)d_in[1];
    const int*   match  = (const int*)d_in[2];
    float* out = (float*)d_out;

    cudaMemsetAsync(out, 0, 2 * sizeof(float));
    ae_kernel<<<B_IMGS, N_KP>>>(pred, target, match, out);
}

// round 13
// speedup vs baseline: 1.1111x; 1.0040x over previous
#include <cuda_runtime.h>

// AELoss: pred/target (64,4,256,256) fp32, match (64,128,2,2) int32.
// out[0] = 0.25 * sum_b pull_b, out[1] = 0.25 * sum_b push_b
//
// pull_b = sum_{n,c} (tl-br)^2 / 2 / N        (since tl-me = (tl-br)/2)
// push_b = sum_{i!=j} relu(1 - |s_i - s_j|) / (N*(N-1)),  s_i = sum_c (tl+br)/2
//
// FINAL — measured floor over 13 rounds (best total 7.968us, kernel 6.496us).
// Session adjudication:
//   WIN     (-2.0us): fire-and-forget RED.ADD tail (no read-back reduction)
//   NEUTRAL: kernel fusion, ILP accumulator splits, cluster gather-halving,
//            256-thread j-split, L2 evict_last policy, atomic trees
//   NEGATIVE: in-kernel fenced zeroing (+1.1us), 2-level completion tree
// Remaining cost = launch ramp (~5K cyc) + graph dispatch (~1.3us):
// not addressable from the .cu. Body is slack under the ramp.

#define B_IMGS 64
#define N_KP   128
#define C_CH   4
#define HW     65536   // 256*256
#define W_DIM  256

__global__ __launch_bounds__(N_KP, 1)
void ae_kernel(const float* __restrict__ pred,
               const float* __restrict__ target,
               const int*   __restrict__ match,
               float*       __restrict__ out) {
    const int b = blockIdx.x;
    const int n = threadIdx.x;

    __shared__ float s_me[N_KP];
    __shared__ float s_red[8];   // 4 warps x 2 values

    // match[b, n, {tl,br}, {y,x}] -- one int4 per (b,n), issued first
    const int4 m = __ldg(reinterpret_cast<const int4*>(match) + b * N_KP + n);
    const int tl_off = m.x * W_DIM + m.y;
    const int br_off = m.z * W_DIM + m.w;

    const float* __restrict__ p = pred   + (size_t)b * C_CH * HW;
    const float* __restrict__ t = target + (size_t)b * C_CH * HW;

    float pull = 0.0f;
    float s    = 0.0f;
    #pragma unroll
    for (int c = 0; c < C_CH; ++c) {
        const float tl = __ldg(p + c * HW + tl_off);
        const float br = __ldg(t + c * HW + br_off);
        const float d = tl - br;
        pull += 0.5f * d * d;
        s    += 0.5f * (tl + br);
    }
    s_me[n] = s;
    __syncthreads();

    // push over all j (smem broadcast, vectorized); subtract the j==n term (==1)
    float push = -1.0f;
    const float4* __restrict__ s4 = reinterpret_cast<const float4*>(s_me);
    #pragma unroll
    for (int j = 0; j < N_KP / 4; ++j) {
        const float4 v = s4[j];
        push += fmaxf(0.0f, 1.0f - fabsf(s - v.x));
        push += fmaxf(0.0f, 1.0f - fabsf(s - v.y));
        push += fmaxf(0.0f, 1.0f - fabsf(s - v.z));
        push += fmaxf(0.0f, 1.0f - fabsf(s - v.w));
    }

    // block reduction of (pull, push)
    #pragma unroll
    for (int off = 16; off > 0; off >>= 1) {
        pull += __shfl_down_sync(0xFFFFFFFFu, pull, off);
        push += __shfl_down_sync(0xFFFFFFFFu, push, off);
    }
    const int warp = n >> 5;
    const int lane = n & 31;
    if (lane == 0) {
        s_red[warp]     = pull;
        s_red[4 + warp] = push;
    }
    __syncthreads();

    // fire-and-forget global reduction: 2 RED.ADD per CTA, no read-back tail
    if (n == 0) {
        const float pu = s_red[0] + s_red[1] + s_red[2] + s_red[3];
        const float ph = s_red[4] + s_red[5] + s_red[6] + s_red[7];
        atomicAdd(&out[0], pu * (0.25f / (float)N_KP));
        atomicAdd(&out[1], ph * (0.25f / (float)(N_KP * (N_KP - 1))));
    }
}

extern "C" void kernel_launch(void* const* d_in, const int* in_sizes, int n_in,
                              void* d_out, int out_size) {
    const float* pred   = (const float*)d_in[0];
    const float* target = (const float*)d_in[1];
    const int*   match  = (const int*)d_in[2];
    float* out = (float*)d_out;

    cudaMemsetAsync(out, 0, 2 * sizeof(float));
    ae_kernel<<<B_IMGS, N_KP>>>(pred, target, match, out);
}

// round 14
// speedup vs baseline: 1.1290x; 1.0161x over previous
#include <cuda_runtime.h>

// AELoss: pred/target (64,4,256,256) fp32, match (64,128,2,2) int32.
// out[0] = 0.25 * sum_b pull_b, out[1] = 0.25 * sum_b push_b
//
// pull_b = sum_{n,c} (tl-br)^2 / 2 / N        (since tl-me = (tl-br)/2)
// push_b = sum_{i!=j} relu(1 - |s_i - s_j|) / (N*(N-1)),  s_i = sum_c (tl+br)/2
//
// FINAL — measured floor over 14 rounds (best total 7.968us, kernel 6.432us).
// Session adjudication:
//   WIN     (-2.0us): fire-and-forget RED.ADD tail (no read-back reduction)
//   NEUTRAL: kernel fusion, ILP splits, cluster gather-halving, 256-thread
//            j-split, L2 evict_last policy, atomic trees
//   NEGATIVE: in-kernel fenced zeroing (+1.1us), 2-level completion tree
// Remaining cost = launch ramp (~5K cyc) + graph dispatch (~1.3us): not
// .cu-addressable. Body is slack under the ramp (4 variants, identical time).

#define B_IMGS 64
#define N_KP   128
#define C_CH   4
#define HW     65536   // 256*256
#define W_DIM  256

__global__ __launch_bounds__(N_KP, 1)
void ae_kernel(const float* __restrict__ pred,
               const float* __restrict__ target,
               const int*   __restrict__ match,
               float*       __restrict__ out) {
    const int b = blockIdx.x;
    const int n = threadIdx.x;

    __shared__ float s_me[N_KP];
    __shared__ float s_red[8];   // 4 warps x 2 values

    // match[b, n, {tl,br}, {y,x}] -- one int4 per (b,n), issued first
    const int4 m = __ldg(reinterpret_cast<const int4*>(match) + b * N_KP + n);
    const int tl_off = m.x * W_DIM + m.y;
    const int br_off = m.z * W_DIM + m.w;

    const float* __restrict__ p = pred   + (size_t)b * C_CH * HW;
    const float* __restrict__ t = target + (size_t)b * C_CH * HW;

    float pull = 0.0f;
    float s    = 0.0f;
    #pragma unroll
    for (int c = 0; c < C_CH; ++c) {
        const float tl = __ldg(p + c * HW + tl_off);
        const float br = __ldg(t + c * HW + br_off);
        const float d = tl - br;
        pull += 0.5f * d * d;
        s    += 0.5f * (tl + br);
    }
    s_me[n] = s;
    __syncthreads();

    // push over all j (smem broadcast, vectorized); subtract the j==n term (==1)
    float push = -1.0f;
    const float4* __restrict__ s4 = reinterpret_cast<const float4*>(s_me);
    #pragma unroll
    for (int j = 0; j < N_KP / 4; ++j) {
        const float4 v = s4[j];
        push += fmaxf(0.0f, 1.0f - fabsf(s - v.x));
        push += fmaxf(0.0f, 1.0f - fabsf(s - v.y));
        push += fmaxf(0.0f, 1.0f - fabsf(s - v.z));
        push += fmaxf(0.0f, 1.0f - fabsf(s - v.w));
    }

    // block reduction of (pull, push)
    #pragma unroll
    for (int off = 16; off > 0; off >>= 1) {
        pull += __shfl_down_sync(0xFFFFFFFFu, pull, off);
        push += __shfl_down_sync(0xFFFFFFFFu, push, off);
    }
    const int warp = n >> 5;
    const int lane = n & 31;
    if (lane == 0) {
        s_red[warp]     = pull;
        s_red[4 + warp] = push;
    }
    __syncthreads();

    // fire-and-forget global reduction, one RED.ADD from each of two warps
    if (n == 0) {
        const float pu = s_red[0] + s_red[1] + s_red[2] + s_red[3];
        atomicAdd(&out[0], pu * (0.25f / (float)N_KP));
    } else if (n == 32) {
        const float ph = s_red[4] + s_red[5] + s_red[6] + s_red[7];
        atomicAdd(&out[1], ph * (0.25f / (float)(N_KP * (N_KP - 1))));
    }
}

extern "C" void kernel_launch(void* const* d_in, const int* in_sizes, int n_in,
                              void* d_out, int out_size) {
    const float* pred   = (const float*)d_in[0];
    const float* target = (const float*)d_in[1];
    const int*   match  = (const int*)d_in[2];
    float* out = (float*)d_out;

    cudaMemsetAsync(out, 0, 2 * sizeof(float));
    ae_kernel<<<B_IMGS, N_KP>>>(pred, target, match, out);
}